// round 2
// baseline (speedup 1.0000x reference)
#include <cuda_runtime.h>
#include <cuda_bf16.h>
#include <cstdint>

// Problem constants (fixed shapes per reference)
#define NROWS 8192
#define DIM   256
#define BM    64
#define BN    128

// SMEM layout (transposed tiles, padded for alignment + bank-conflict freedom)
#define XS_STRIDE 68   // multiple of 4 (16B-aligned float4 rows), bank shift 4/k
#define YS_STRIDE 130  // even (8B-aligned float2), 32-consecutive-float reads cover all banks
#define SMEM_FLOATS (DIM * XS_STRIDE + DIM * YS_STRIDE)
#define SMEM_BYTES  (SMEM_FLOATS * 4)   // 202,752 B < 227 KB

// Normalized-input scratch (device globals: no allocation allowed)
__device__ float g_Xn[NROWS * DIM];
__device__ float g_Yn[NROWS * DIM];

// ---------------------------------------------------------------------------
// packed f32x2 helpers (FFMA2 path: 2x fp32 FMA throughput on sm_103a)
// ---------------------------------------------------------------------------
__device__ __forceinline__ unsigned long long ffma2(unsigned long long a,
                                                    unsigned long long b,
                                                    unsigned long long c) {
    unsigned long long d;
    asm("fma.rn.f32x2 %0, %1, %2, %3;" : "=l"(d) : "l"(a), "l"(b), "l"(c));
    return d;
}
__device__ __forceinline__ unsigned long long pack2(float x, float y) {
    unsigned long long d;
    asm("mov.b64 %0, {%1, %2};" : "=l"(d) : "f"(x), "f"(y));
    return d;
}
__device__ __forceinline__ void unpack2(unsigned long long v, float& lo, float& hi) {
    asm("mov.b64 {%0, %1}, %2;" : "=f"(lo), "=f"(hi) : "l"(v));
}

// ---------------------------------------------------------------------------
// Row normalization: one block per row, 256 threads = 256 elements
// ---------------------------------------------------------------------------
__global__ void __launch_bounds__(256) norm_kernel(const float* __restrict__ in, int which) {
    int row = blockIdx.x;
    int t = threadIdx.x;
    float v = in[row * DIM + t];
    float ss = v * v;
    #pragma unroll
    for (int o = 16; o; o >>= 1) ss += __shfl_xor_sync(0xFFFFFFFFu, ss, o);
    __shared__ float ws[8];
    if ((t & 31) == 0) ws[t >> 5] = ss;
    __syncthreads();
    float tot = 0.0f;
    #pragma unroll
    for (int w = 0; w < 8; w++) tot += ws[w];
    float scale = 1.0f / fmaxf(sqrtf(tot), 1e-8f);
    float* dst = which ? g_Yn : g_Xn;
    dst[row * DIM + t] = v * scale;
}

// ---------------------------------------------------------------------------
// Fused GEMM (xn @ yn^T) + Normal(1, 0.3).log_prob epilogue + row-min
// Block: 256 threads (16 tx x 16 ty). Each thread: 4 n-rows x 4 m-pairs.
// Block covers BM=64 rows of n against all 8192 m (loop over 64 BN-tiles).
// ---------------------------------------------------------------------------
__global__ void __launch_bounds__(256, 1) gemm_min_kernel(float* __restrict__ out) {
    extern __shared__ float smem[];
    float* Xs = smem;                       // [DIM][XS_STRIDE], transposed: Xs[k][n]
    float* Ys = smem + DIM * XS_STRIDE;     // [DIM][YS_STRIDE], transposed: Ys[k][m]

    const int tid = threadIdx.x;
    const int tx = tid & 15;
    const int ty = tid >> 4;
    const int nBase = blockIdx.x * BM;

    // Load X tile (transposed into SMEM), once per block
    for (int idx = tid; idx < BM * DIM; idx += 256) {
        int n = idx >> 8;          // DIM == 256
        int k = idx & 255;
        Xs[k * XS_STRIDE + n] = g_Xn[(nBase + n) * DIM + k];
    }

    const float INV_SIGMA = 1.0f / 0.3f;
    const float LOGC = 0.28503427112126587f;   // -log(sigma) - 0.5*log(2*pi)
    const float INF = __int_as_float(0x7f800000);

    float cmin[4] = {INF, INF, INF, INF};

    for (int mt = 0; mt < NROWS / BN; ++mt) {
        __syncthreads();
        const int mBase = mt * BN;
        // Load Y tile (transposed)
        for (int idx = tid; idx < BN * DIM; idx += 256) {
            int m = idx >> 8;
            int k = idx & 255;
            Ys[k * YS_STRIDE + m] = g_Yn[(mBase + m) * DIM + k];
        }
        __syncthreads();

        unsigned long long acc[4][4];
        #pragma unroll
        for (int i = 0; i < 4; i++)
            #pragma unroll
            for (int j = 0; j < 4; j++)
                acc[i][j] = 0ull;  // bit pattern of (0.f, 0.f)

        #pragma unroll 4
        for (int k = 0; k < DIM; k++) {
            // a: 4 n-values, broadcast across tx (conflict-free)
            const float4 a4 = *(const float4*)&Xs[k * XS_STRIDE + ty * 4];
            unsigned long long ap[4];
            ap[0] = pack2(a4.x, a4.x);
            ap[1] = pack2(a4.y, a4.y);
            ap[2] = pack2(a4.z, a4.z);
            ap[3] = pack2(a4.w, a4.w);
            // b: 4 m-pairs; 16 lanes read 32 consecutive floats -> all 32 banks once
            unsigned long long b[4];
            #pragma unroll
            for (int jp = 0; jp < 4; jp++)
                b[jp] = *(const unsigned long long*)&Ys[k * YS_STRIDE + jp * 32 + tx * 2];
            #pragma unroll
            for (int i = 0; i < 4; i++)
                #pragma unroll
                for (int jp = 0; jp < 4; jp++)
                    acc[i][jp] = ffma2(ap[i], b[jp], acc[i][jp]);
        }

        // Epilogue: C(M) = -exp(logp)*logp, logp = -0.5*((M-1)/sigma)^2 + LOGC
        #pragma unroll
        for (int i = 0; i < 4; i++) {
            #pragma unroll
            for (int jp = 0; jp < 4; jp++) {
                float m0, m1;
                unpack2(acc[i][jp], m0, m1);
                float z0 = (m0 - 1.0f) * INV_SIGMA;
                float z1 = (m1 - 1.0f) * INV_SIGMA;
                float lp0 = fmaf(-0.5f * z0, z0, LOGC);
                float lp1 = fmaf(-0.5f * z1, z1, LOGC);
                float c0 = -__expf(lp0) * lp0;
                float c1 = -__expf(lp1) * lp1;
                cmin[i] = fminf(cmin[i], fminf(c0, c1));
            }
        }
    }

    // Cross-thread (tx) min reduction per n-row via SMEM, then write out
    __syncthreads();
    float* red = smem;  // reuse: [BM][16]
    #pragma unroll
    for (int i = 0; i < 4; i++)
        red[(ty * 4 + i) * 16 + tx] = cmin[i];
    __syncthreads();
    if (tid < BM) {
        float v = INF;
        #pragma unroll
        for (int t = 0; t < 16; t++)
            v = fminf(v, red[tid * 16 + t]);
        out[nBase + tid] = v;
    }
}

// ---------------------------------------------------------------------------
extern "C" void kernel_launch(void* const* d_in, const int* in_sizes, int n_in,
                              void* d_out, int out_size) {
    const float* Ex = (const float*)d_in[0];
    const float* Ey = (const float*)d_in[1];
    float* out = (float*)d_out;

    norm_kernel<<<NROWS, 256>>>(Ex, 0);
    norm_kernel<<<NROWS, 256>>>(Ey, 1);

    cudaFuncSetAttribute(gemm_min_kernel,
                         cudaFuncAttributeMaxDynamicSharedMemorySize, SMEM_BYTES);
    gemm_min_kernel<<<NROWS / BM, 256, SMEM_BYTES>>>(out);
}

// round 4
// speedup vs baseline: 3.9897x; 3.9897x over previous
#include <cuda_runtime.h>
#include <cuda_bf16.h>
#include <cstdint>

#define NROWS 8192
#define DIM   256
#define GY    2
#define NMT   32                 // m-tiles (128 wide) per CTA (per gy slice)
#define NCHUNK (NMT * 4)         // 64-k chunks per CTA

// ---------------- device scratch (no allocation allowed) -------------------
__device__ __nv_bfloat16 g_Xhi[NROWS * DIM];
__device__ __nv_bfloat16 g_Xlo[NROWS * DIM];
__device__ __nv_bfloat16 g_Yhi[NROWS * DIM];
__device__ __nv_bfloat16 g_Ylo[NROWS * DIM];
__device__ float g_minM[GY * NROWS];
__device__ float g_cex [GY * NROWS];

#define INVS 3.33333333333333f
#define LOGC 0.28503427112126587f      /* -log(0.3) - 0.5*log(2*pi) */

// SMEM map: A tiles [arr(hi/lo)][kc 0..3] of [128 rows][64 k] SW128 (8x16KB),
// then B stages [s][hi/lo][128][64] (3x32KB). Total 229376 B.
#define SM_A 0
#define SM_B (8 * 16384)
#define SMEM_TOTAL (SM_B + 3 * 32768)

// ---------------- helpers --------------------------------------------------
__device__ __forceinline__ uint32_t smem_u32(const void* p) {
    uint32_t a;
    asm("{ .reg .u64 t; cvta.to.shared.u64 t, %1; cvt.u32.u64 %0, t; }" : "=r"(a) : "l"(p));
    return a;
}
__device__ __forceinline__ uint64_t gmem_u64(const void* p) {
    uint64_t a;
    asm("cvta.to.global.u64 %0, %1;" : "=l"(a) : "l"(p));
    return a;
}
#define SWZ128(x) ((x) ^ (((x) >> 3) & 0x70))

#define CPASYNC16(dst, src) \
    asm volatile("cp.async.cg.shared.global [%0], [%1], 16;" :: "r"(dst), "l"(src) : "memory")
#define CP_COMMIT()  asm volatile("cp.async.commit_group;" ::: "memory")
#define CP_WAIT(n)   asm volatile("cp.async.wait_group %0;" :: "n"(n) : "memory")

__device__ __forceinline__ void ldsm_x4(uint32_t r[4], uint32_t addr) {
    asm volatile("ldmatrix.sync.aligned.m8n8.x4.shared.b16 {%0,%1,%2,%3}, [%4];"
                 : "=r"(r[0]), "=r"(r[1]), "=r"(r[2]), "=r"(r[3]) : "r"(addr));
}
__device__ __forceinline__ void mma16816(float c[4], const uint32_t a[4], const uint32_t b[2]) {
    asm("mma.sync.aligned.m16n8k16.row.col.f32.bf16.bf16.f32 "
        "{%0,%1,%2,%3}, {%4,%5,%6,%7}, {%8,%9}, {%0,%1,%2,%3};"
        : "+f"(c[0]), "+f"(c[1]), "+f"(c[2]), "+f"(c[3])
        : "r"(a[0]), "r"(a[1]), "r"(a[2]), "r"(a[3]), "r"(b[0]), "r"(b[1]));
}

// ---------------- normalize + bf16 hi/lo split -----------------------------
__global__ void __launch_bounds__(256) norm_split_kernel(const float* __restrict__ in, int which) {
    int row = blockIdx.x, t = threadIdx.x;
    float v = in[row * DIM + t];
    float ss = v * v;
    #pragma unroll
    for (int o = 16; o; o >>= 1) ss += __shfl_xor_sync(0xFFFFFFFFu, ss, o);
    __shared__ float ws[8];
    if ((t & 31) == 0) ws[t >> 5] = ss;
    __syncthreads();
    float tot = 0.0f;
    #pragma unroll
    for (int w = 0; w < 8; w++) tot += ws[w];
    float x = v * (1.0f / fmaxf(sqrtf(tot), 1e-8f));
    __nv_bfloat16 h = __float2bfloat16(x);
    __nv_bfloat16 l = __float2bfloat16(x - __bfloat162float(h));
    (which ? g_Yhi : g_Xhi)[row * DIM + t] = h;
    (which ? g_Ylo : g_Xlo)[row * DIM + t] = l;
}

// ---------------- pipelined HMMA GEMM + running-min ------------------------
__global__ void __launch_bounds__(256, 1) gemm_min_kernel() {
    extern __shared__ char smem[];
    const uint32_t sb = smem_u32(smem);
    const int tid = threadIdx.x, lane = tid & 31, wid = tid >> 5;
    const int warp_m = wid & 1;       // 2 warps in M (64 each)
    const int warp_n = wid >> 1;      // 4 warps in N (32 each)
    const int nBase = blockIdx.x * 128;
    const int gy = blockIdx.y;
    const float INF = __int_as_float(0x7f800000);

    // ---- Prologue: resident A tiles (X hi/lo), SW128 ----
    {
        const uint64_t xh = gmem_u64(g_Xhi), xl = gmem_u64(g_Xlo);
        #pragma unroll 4
        for (int i = 0; i < 32; i++) {
            int idx = tid + 256 * i;
            int tile = idx >> 10, rem = idx & 1023;
            int row = rem >> 3, seg = rem & 7;
            int arr = tile >> 2, kc = tile & 3;
            uint64_t src = (arr ? xl : xh) + 2ull * ((uint64_t)(nBase + row) * DIM + kc * 64 + seg * 8);
            uint32_t dst = sb + SM_A + tile * 16384 + SWZ128(row * 128 + seg * 16);
            CPASYNC16(dst, src);
        }
        CP_COMMIT(); CP_WAIT(0);
        __syncthreads();
    }

    // ---- B chunk producer (all threads) ----
    const uint64_t yh = gmem_u64(g_Yhi), yl = gmem_u64(g_Ylo);
    auto issue_chunk = [&](int ci) {
        int s = ci % 3, mt = ci >> 2, kc = ci & 3;
        int mBase = gy * (NROWS / GY) + mt * 128;
        #pragma unroll
        for (int i = 0; i < 8; i++) {
            int idx = tid + 256 * i;
            int arr = idx >> 10, rem = idx & 1023;
            int row = rem >> 3, seg = rem & 7;
            uint64_t src = (arr ? yl : yh) + 2ull * ((uint64_t)(mBase + row) * DIM + kc * 64 + seg * 8);
            uint32_t dst = sb + SM_B + s * 32768 + arr * 16384 + SWZ128(row * 128 + seg * 16);
            CPASYNC16(dst, src);
        }
    };

    // ---- per-thread ldmatrix address components ----
    const uint32_t xor7 = (lane & 7) << 4;
    const int aq = lane >> 3;
    const uint32_t a_k16 = (aq >> 1) << 4;                 // k-half byte offset (0/16)
    const uint32_t b_k16 = ((lane >> 3) & 1) << 4;
    uint32_t rowA[4], rowB[2];
    #pragma unroll
    for (int mt = 0; mt < 4; mt++)
        rowA[mt] = (uint32_t)(warp_m * 64 + mt * 16 + ((aq & 1) << 3) + (lane & 7)) * 128;
    #pragma unroll
    for (int g = 0; g < 2; g++)
        rowB[g] = (uint32_t)(warp_n * 32 + g * 16 + (((lane >> 4) & 1) << 3) + (lane & 7)) * 128;

    float acc[4][4][4];
    #pragma unroll
    for (int mt = 0; mt < 4; mt++)
        #pragma unroll
        for (int nt = 0; nt < 4; nt++)
            #pragma unroll
            for (int e = 0; e < 4; e++) acc[mt][nt][e] = 0.0f;
    float rowmin[8], rowcex[8];
    #pragma unroll
    for (int i = 0; i < 8; i++) { rowmin[i] = INF; rowcex[i] = INF; }

    issue_chunk(0); CP_COMMIT();
    issue_chunk(1); CP_COMMIT();

    #pragma unroll 1
    for (int ci = 0; ci < NCHUNK; ci++) {
        CP_WAIT(1);
        __syncthreads();
        if (ci + 2 < NCHUNK) issue_chunk(ci + 2);
        CP_COMMIT();

        const int s = ci % 3, kc = ci & 3;
        const uint32_t aHi = sb + SM_A + kc * 16384;
        const uint32_t aLo = aHi + 4 * 16384;
        const uint32_t bHi = sb + SM_B + s * 32768;
        const uint32_t bLo = bHi + 16384;

        #pragma unroll
        for (int ks = 0; ks < 4; ks++) {
            const uint32_t kbA = ((uint32_t)(ks * 32) + a_k16) ^ xor7;
            const uint32_t kbB = ((uint32_t)(ks * 32) + b_k16) ^ xor7;
            uint32_t Ah[4][4], Al[4][4], Bh[4][2], Bl[4][2];
            #pragma unroll
            for (int g = 0; g < 2; g++) {
                uint32_t r[4];
                ldsm_x4(r, bHi + rowB[g] + kbB);
                Bh[2*g][0] = r[0]; Bh[2*g][1] = r[1]; Bh[2*g+1][0] = r[2]; Bh[2*g+1][1] = r[3];
                ldsm_x4(r, bLo + rowB[g] + kbB);
                Bl[2*g][0] = r[0]; Bl[2*g][1] = r[1]; Bl[2*g+1][0] = r[2]; Bl[2*g+1][1] = r[3];
            }
            #pragma unroll
            for (int mt = 0; mt < 4; mt++) {
                ldsm_x4(Ah[mt], aHi + rowA[mt] + kbA);
                ldsm_x4(Al[mt], aLo + rowA[mt] + kbA);
            }
            #pragma unroll
            for (int mt = 0; mt < 4; mt++)
                #pragma unroll
                for (int nt = 0; nt < 4; nt++) {
                    mma16816(acc[mt][nt], Ah[mt], Bh[nt]);
                    mma16816(acc[mt][nt], Ah[mt], Bl[nt]);
                    mma16816(acc[mt][nt], Al[mt], Bh[nt]);
                }
        }

        if ((ci & 3) == 3) {   // m-tile complete: fold into running row-mins
            #pragma unroll
            for (int mt = 0; mt < 4; mt++)
                #pragma unroll
                for (int nt = 0; nt < 4; nt++)
                    #pragma unroll
                    for (int e = 0; e < 4; e++) {
                        float M = acc[mt][nt][e];
                        acc[mt][nt][e] = 0.0f;
                        int ri = mt * 2 + (e >> 1);
                        if (M > 0.5f) {      // cold exact path (monotonicity edge)
                            float z = (M - 1.0f) * INVS;
                            float lp = fmaf(-0.5f * z, z, LOGC);
                            rowcex[ri] = fminf(rowcex[ri], -expf(lp) * lp);
                        } else {
                            rowmin[ri] = fminf(rowmin[ri], M);
                        }
                    }
        }
    }

    // ---- cross-warp reduction (reuse A smem region) ----
    __syncthreads();
    float* redM = (float*)smem;             // [128][16]
    float* redC = redM + 128 * 16;
    const int slot = warp_n * 4 + (lane & 3);
    #pragma unroll
    for (int i = 0; i < 8; i++) {
        int nl = warp_m * 64 + (i >> 1) * 16 + (i & 1) * 8 + (lane >> 2);
        redM[nl * 16 + slot] = rowmin[i];
        redC[nl * 16 + slot] = rowcex[i];
    }
    __syncthreads();
    if (tid < 128) {
        float m = INF, c = INF;
        #pragma unroll
        for (int k = 0; k < 16; k++) {
            m = fminf(m, redM[tid * 16 + k]);
            c = fminf(c, redC[tid * 16 + k]);
        }
        g_minM[gy * NROWS + nBase + tid] = m;
        g_cex [gy * NROWS + nBase + tid] = c;
    }
}

// ---------------- final combine over the two m-halves ----------------------
__global__ void __launch_bounds__(256) combine_kernel(float* __restrict__ out) {
    int n = blockIdx.x * 256 + threadIdx.x;
    float m  = fminf(g_minM[n], g_minM[NROWS + n]);
    float ce = fminf(g_cex[n],  g_cex[NROWS + n]);
    float C = __int_as_float(0x7f800000);
    if (m < 2.0f) {
        float z = (m - 1.0f) * INVS;
        float lp = fmaf(-0.5f * z, z, LOGC);
        C = -expf(lp) * lp;
    }
    out[n] = fminf(C, ce);
}

// ---------------------------------------------------------------------------
extern "C" void kernel_launch(void* const* d_in, const int* in_sizes, int n_in,
                              void* d_out, int out_size) {
    const float* Ex = (const float*)d_in[0];
    const float* Ey = (const float*)d_in[1];
    float* out = (float*)d_out;

    norm_split_kernel<<<NROWS, 256>>>(Ex, 0);
    norm_split_kernel<<<NROWS, 256>>>(Ey, 1);

    cudaFuncSetAttribute(gemm_min_kernel,
                         cudaFuncAttributeMaxDynamicSharedMemorySize, SMEM_TOTAL);
    dim3 grid(NROWS / 128, GY);
    gemm_min_kernel<<<grid, 256, SMEM_TOTAL>>>();

    combine_kernel<<<NROWS / 256, 256>>>(out);
}

// round 5
// speedup vs baseline: 5.2742x; 1.3220x over previous
#include <cuda_runtime.h>
#include <cuda_fp16.h>
#include <cstdint>

#define NROWS 8192
#define DIM   256
#define GY    2
#define NMT   32                 // m-tiles (128 wide) per CTA (per gy slice)
#define NCHUNK (NMT * 4)         // 64-k chunks per CTA
#define NSTAGE 5

// ---------------- device scratch (no allocation allowed) -------------------
__device__ __half g_Xhi[NROWS * DIM];
__device__ __half g_Yhi[NROWS * DIM];
__device__ __half g_Ylo[NROWS * DIM];
__device__ float g_minM[GY * NROWS];
__device__ float g_cex [GY * NROWS];

#define INVS 3.33333333333333f
#define LOGC 0.28503427112126587f      /* -log(0.3) - 0.5*log(2*pi) */

// SMEM: A (X hi) 4 tiles [128r][64k] SW128 = 64KB; B stages [s][hi/lo][128][64]
#define SM_A 0
#define SM_B (4 * 16384)
#define SMEM_TOTAL (SM_B + NSTAGE * 32768)   /* 65536 + 163840 = 229376 */

// ---------------- helpers --------------------------------------------------
__device__ __forceinline__ uint32_t smem_u32(const void* p) {
    uint32_t a;
    asm("{ .reg .u64 t; cvta.to.shared.u64 t, %1; cvt.u32.u64 %0, t; }" : "=r"(a) : "l"(p));
    return a;
}
__device__ __forceinline__ uint64_t gmem_u64(const void* p) {
    uint64_t a;
    asm("cvta.to.global.u64 %0, %1;" : "=l"(a) : "l"(p));
    return a;
}
#define SWZ128(x) ((x) ^ (((x) >> 3) & 0x70))

#define CPASYNC16(dst, src) \
    asm volatile("cp.async.cg.shared.global [%0], [%1], 16;" :: "r"(dst), "l"(src) : "memory")
#define CP_COMMIT()  asm volatile("cp.async.commit_group;" ::: "memory")
#define CP_WAIT(n)   asm volatile("cp.async.wait_group %0;" :: "n"(n) : "memory")

__device__ __forceinline__ void ldsm_x4(uint32_t r[4], uint32_t addr) {
    asm volatile("ldmatrix.sync.aligned.m8n8.x4.shared.b16 {%0,%1,%2,%3}, [%4];"
                 : "=r"(r[0]), "=r"(r[1]), "=r"(r[2]), "=r"(r[3]) : "r"(addr));
}
__device__ __forceinline__ void mma16816(float c[4], const uint32_t a[4], const uint32_t b[2]) {
    asm("mma.sync.aligned.m16n8k16.row.col.f32.f16.f16.f32 "
        "{%0,%1,%2,%3}, {%4,%5,%6,%7}, {%8,%9}, {%0,%1,%2,%3};"
        : "+f"(c[0]), "+f"(c[1]), "+f"(c[2]), "+f"(c[3])
        : "r"(a[0]), "r"(a[1]), "r"(a[2]), "r"(a[3]), "r"(b[0]), "r"(b[1]));
}

// ---------------- normalize + fp16 hi/lo split (warp per row) --------------
__global__ void __launch_bounds__(256) norm_split_kernel(const float* __restrict__ in, int which) {
    const int w = (blockIdx.x << 3) + (threadIdx.x >> 5);   // row
    const int lane = threadIdx.x & 31;
    const float4* src = (const float4*)(in + w * DIM) + lane * 2;
    float4 v0 = src[0], v1 = src[1];
    float ss = v0.x*v0.x + v0.y*v0.y + v0.z*v0.z + v0.w*v0.w
             + v1.x*v1.x + v1.y*v1.y + v1.z*v1.z + v1.w*v1.w;
    #pragma unroll
    for (int o = 16; o; o >>= 1) ss += __shfl_xor_sync(0xFFFFFFFFu, ss, o);
    const float sc = 1.0f / fmaxf(sqrtf(ss), 1e-8f);
    float x[8] = {v0.x*sc, v0.y*sc, v0.z*sc, v0.w*sc, v1.x*sc, v1.y*sc, v1.z*sc, v1.w*sc};
    __half h[8]; float l[8];
    #pragma unroll
    for (int i = 0; i < 8; i++) { h[i] = __float2half_rn(x[i]); l[i] = x[i] - __half2float(h[i]); }
    __half2 hp[4];
    #pragma unroll
    for (int i = 0; i < 4; i++) hp[i] = __halves2half2(h[2*i], h[2*i+1]);
    if (which) {
        *(uint4*)(g_Yhi + w * DIM + lane * 8) = *(uint4*)hp;
        __half2 lp[4];
        #pragma unroll
        for (int i = 0; i < 4; i++) lp[i] = __floats2half2_rn(l[2*i], l[2*i+1]);
        *(uint4*)(g_Ylo + w * DIM + lane * 8) = *(uint4*)lp;
    } else {
        *(uint4*)(g_Xhi + w * DIM + lane * 8) = *(uint4*)hp;
    }
}

// ---------------- pipelined HMMA GEMM + running-min ------------------------
__global__ void __launch_bounds__(256, 1) gemm_min_kernel() {
    extern __shared__ char smem[];
    const uint32_t sb = smem_u32(smem);
    const int tid = threadIdx.x, lane = tid & 31, wid = tid >> 5;
    const int warp_m = wid & 1;       // 2 warps in M (64 each)
    const int warp_n = wid >> 1;      // 4 warps in N (32 each)
    const int nBase = blockIdx.x * 128;
    const int gy = blockIdx.y;
    const float INF = __int_as_float(0x7f800000);

    // ---- Prologue: resident A tiles (X hi only), SW128 ----
    {
        const uint64_t xh = gmem_u64(g_Xhi);
        #pragma unroll 4
        for (int i = 0; i < 16; i++) {
            int idx = tid + 256 * i;
            int kc = idx >> 10, rem = idx & 1023;
            int row = rem >> 3, seg = rem & 7;
            uint64_t src = xh + 2ull * ((uint64_t)(nBase + row) * DIM + kc * 64 + seg * 8);
            uint32_t dst = sb + SM_A + kc * 16384 + SWZ128(row * 128 + seg * 16);
            CPASYNC16(dst, src);
        }
        CP_COMMIT(); CP_WAIT(0);
        __syncthreads();
    }

    // ---- B chunk producer (all threads) ----
    const uint64_t yh = gmem_u64(g_Yhi), yl = gmem_u64(g_Ylo);
    auto issue_chunk = [&](int ci) {
        int s = ci % NSTAGE, mt = ci >> 2, kc = ci & 3;
        int mBase = gy * (NROWS / GY) + mt * 128;
        #pragma unroll
        for (int i = 0; i < 8; i++) {
            int idx = tid + 256 * i;
            int arr = idx >> 10, rem = idx & 1023;
            int row = rem >> 3, seg = rem & 7;
            uint64_t src = (arr ? yl : yh) + 2ull * ((uint64_t)(mBase + row) * DIM + kc * 64 + seg * 8);
            uint32_t dst = sb + SM_B + s * 32768 + arr * 16384 + SWZ128(row * 128 + seg * 16);
            CPASYNC16(dst, src);
        }
    };

    // ---- per-thread ldmatrix address components ----
    const uint32_t xor7 = (lane & 7) << 4;
    const int aq = lane >> 3;
    const uint32_t a_k16 = (aq >> 1) << 4;
    const uint32_t b_k16 = ((lane >> 3) & 1) << 4;
    uint32_t rowA[4], rowB[2];
    #pragma unroll
    for (int mt = 0; mt < 4; mt++)
        rowA[mt] = (uint32_t)(warp_m * 64 + mt * 16 + ((aq & 1) << 3) + (lane & 7)) * 128;
    #pragma unroll
    for (int g = 0; g < 2; g++)
        rowB[g] = (uint32_t)(warp_n * 32 + g * 16 + (((lane >> 4) & 1) << 3) + (lane & 7)) * 128;

    float acc[4][4][4];
    #pragma unroll
    for (int mt = 0; mt < 4; mt++)
        #pragma unroll
        for (int nt = 0; nt < 4; nt++)
            #pragma unroll
            for (int e = 0; e < 4; e++) acc[mt][nt][e] = 0.0f;
    float rowmin[8], rowcex[8];
    #pragma unroll
    for (int i = 0; i < 8; i++) { rowmin[i] = INF; rowcex[i] = INF; }

    issue_chunk(0); CP_COMMIT();
    issue_chunk(1); CP_COMMIT();
    issue_chunk(2); CP_COMMIT();
    issue_chunk(3); CP_COMMIT();

    #pragma unroll 1
    for (int ci = 0; ci < NCHUNK; ci++) {
        CP_WAIT(3);
        __syncthreads();
        if (ci + 4 < NCHUNK) issue_chunk(ci + 4);
        CP_COMMIT();

        const int s = ci % NSTAGE, kc = ci & 3;
        const uint32_t aHi = sb + SM_A + kc * 16384;
        const uint32_t bHi = sb + SM_B + s * 32768;
        const uint32_t bLo = bHi + 16384;

        #pragma unroll
        for (int ks = 0; ks < 4; ks++) {
            const uint32_t kbA = ((uint32_t)(ks * 32) + a_k16) ^ xor7;
            const uint32_t kbB = ((uint32_t)(ks * 32) + b_k16) ^ xor7;
            uint32_t Ah[4][4], Bh[4][2], Bl[4][2];
            #pragma unroll
            for (int g = 0; g < 2; g++) {
                uint32_t r[4];
                ldsm_x4(r, bHi + rowB[g] + kbB);
                Bh[2*g][0] = r[0]; Bh[2*g][1] = r[1]; Bh[2*g+1][0] = r[2]; Bh[2*g+1][1] = r[3];
                ldsm_x4(r, bLo + rowB[g] + kbB);
                Bl[2*g][0] = r[0]; Bl[2*g][1] = r[1]; Bl[2*g+1][0] = r[2]; Bl[2*g+1][1] = r[3];
            }
            #pragma unroll
            for (int mt = 0; mt < 4; mt++)
                ldsm_x4(Ah[mt], aHi + rowA[mt] + kbA);
            #pragma unroll
            for (int mt = 0; mt < 4; mt++)
                #pragma unroll
                for (int nt = 0; nt < 4; nt++) {
                    mma16816(acc[mt][nt], Ah[mt], Bh[nt]);
                    mma16816(acc[mt][nt], Ah[mt], Bl[nt]);
                }
        }

        if ((ci & 3) == 3) {   // m-tile complete: fold into running row-mins
            #pragma unroll
            for (int mt = 0; mt < 4; mt++)
                #pragma unroll
                for (int nt = 0; nt < 4; nt++)
                    #pragma unroll
                    for (int e = 0; e < 4; e++) {
                        float M = acc[mt][nt][e];
                        acc[mt][nt][e] = 0.0f;
                        int ri = mt * 2 + (e >> 1);
                        if (M > 0.5f) {      // cold exact path (monotonicity edge)
                            float z = (M - 1.0f) * INVS;
                            float lp = fmaf(-0.5f * z, z, LOGC);
                            rowcex[ri] = fminf(rowcex[ri], -expf(lp) * lp);
                        } else {
                            rowmin[ri] = fminf(rowmin[ri], M);
                        }
                    }
        }
    }

    // ---- cross-warp reduction (reuse A smem region) ----
    __syncthreads();
    float* redM = (float*)smem;             // [128][16]
    float* redC = redM + 128 * 16;
    const int slot = warp_n * 4 + (lane & 3);
    #pragma unroll
    for (int i = 0; i < 8; i++) {
        int nl = warp_m * 64 + (i >> 1) * 16 + (i & 1) * 8 + (lane >> 2);
        redM[nl * 16 + slot] = rowmin[i];
        redC[nl * 16 + slot] = rowcex[i];
    }
    __syncthreads();
    if (tid < 128) {
        float m = INF, c = INF;
        #pragma unroll
        for (int k = 0; k < 16; k++) {
            m = fminf(m, redM[tid * 16 + k]);
            c = fminf(c, redC[tid * 16 + k]);
        }
        g_minM[gy * NROWS + nBase + tid] = m;
        g_cex [gy * NROWS + nBase + tid] = c;
    }
}

// ---------------- final combine over the two m-halves ----------------------
__global__ void __launch_bounds__(256) combine_kernel(float* __restrict__ out) {
    int n = blockIdx.x * 256 + threadIdx.x;
    float m  = fminf(g_minM[n], g_minM[NROWS + n]);
    float ce = fminf(g_cex[n],  g_cex[NROWS + n]);
    float C = __int_as_float(0x7f800000);
    if (m < 2.0f) {
        float z = (m - 1.0f) * INVS;
        float lp = fmaf(-0.5f * z, z, LOGC);
        C = -expf(lp) * lp;
    }
    out[n] = fminf(C, ce);
}

// ---------------------------------------------------------------------------
extern "C" void kernel_launch(void* const* d_in, const int* in_sizes, int n_in,
                              void* d_out, int out_size) {
    const float* Ex = (const float*)d_in[0];
    const float* Ey = (const float*)d_in[1];
    float* out = (float*)d_out;

    norm_split_kernel<<<NROWS / 8, 256>>>(Ex, 0);
    norm_split_kernel<<<NROWS / 8, 256>>>(Ey, 1);

    cudaFuncSetAttribute(gemm_min_kernel,
                         cudaFuncAttributeMaxDynamicSharedMemorySize, SMEM_TOTAL);
    dim3 grid(NROWS / 128, GY);
    gemm_min_kernel<<<grid, 256, SMEM_TOTAL>>>();

    combine_kernel<<<NROWS / 256, 256>>>(out);
}

// round 6
// speedup vs baseline: 8.8547x; 1.6789x over previous
#include <cuda_runtime.h>
#include <cuda_fp16.h>
#include <cstdint>

#define NROWS 8192
#define DIM   256
#define NTI   64                  // n-tiles (128 rows each)
#define MTI   64                  // m-tiles (128 rows each)
#define UNITS (NTI * MTI)
#define GRID  148
#define NSTAGE 6

// ---------------- device scratch (no allocation allowed) -------------------
__device__ __half g_Xhi[NROWS * DIM];
__device__ __half g_Yhi[NROWS * DIM];
__device__ float g_minM[NROWS];
__device__ float g_cex [NROWS];

#define INVS 3.33333333333333f
#define LOGC 0.28503427112126587f      /* -log(0.3) - 0.5*log(2*pi) */

// SMEM: A (X hi) 4 tiles [128r][64k] SW128 = 64KB; B stages [s][128][64] 16KB ea
#define SM_A 0
#define SM_B (4 * 16384)
#define SMEM_TOTAL (SM_B + NSTAGE * 16384)   /* 65536 + 98304 = 163840 */

// ---------------- helpers --------------------------------------------------
__device__ __forceinline__ uint32_t smem_u32(const void* p) {
    uint32_t a;
    asm("{ .reg .u64 t; cvta.to.shared.u64 t, %1; cvt.u32.u64 %0, t; }" : "=r"(a) : "l"(p));
    return a;
}
__device__ __forceinline__ uint64_t gmem_u64(const void* p) {
    uint64_t a;
    asm("cvta.to.global.u64 %0, %1;" : "=l"(a) : "l"(p));
    return a;
}
#define SWZ128(x) ((x) ^ (((x) >> 3) & 0x70))

#define CPASYNC16(dst, src) \
    asm volatile("cp.async.cg.shared.global [%0], [%1], 16;" :: "r"(dst), "l"(src) : "memory")
#define CP_COMMIT()  asm volatile("cp.async.commit_group;" ::: "memory")
#define CP_WAIT(n)   asm volatile("cp.async.wait_group %0;" :: "n"(n) : "memory")

__device__ __forceinline__ void ldsm_x4(uint32_t r[4], uint32_t addr) {
    asm volatile("ldmatrix.sync.aligned.m8n8.x4.shared.b16 {%0,%1,%2,%3}, [%4];"
                 : "=r"(r[0]), "=r"(r[1]), "=r"(r[2]), "=r"(r[3]) : "r"(addr));
}
__device__ __forceinline__ void mma16816(float c[4], const uint32_t a[4], const uint32_t b[2]) {
    asm("mma.sync.aligned.m16n8k16.row.col.f32.f16.f16.f32 "
        "{%0,%1,%2,%3}, {%4,%5,%6,%7}, {%8,%9}, {%0,%1,%2,%3};"
        : "+f"(c[0]), "+f"(c[1]), "+f"(c[2]), "+f"(c[3])
        : "r"(a[0]), "r"(a[1]), "r"(a[2]), "r"(a[3]), "r"(b[0]), "r"(b[1]));
}
// sign-aware atomic float min (target initialized to +INF)
__device__ __forceinline__ void atomicMinF(float* a, float v) {
    if (v >= 0.0f) atomicMin((int*)a, __float_as_int(v));
    else           atomicMax((unsigned int*)a, __float_as_uint(v));
}

// ---------------- init (graph-replay-safe reset of accumulators) -----------
__global__ void __launch_bounds__(256) init_kernel() {
    int n = blockIdx.x * 256 + threadIdx.x;
    g_minM[n] = __int_as_float(0x7f800000);
    g_cex [n] = __int_as_float(0x7f800000);
}

// ---------------- normalize -> fp16 (warp per row) -------------------------
__global__ void __launch_bounds__(256) norm_kernel(const float* __restrict__ in, int which) {
    const int w = (blockIdx.x << 3) + (threadIdx.x >> 5);
    const int lane = threadIdx.x & 31;
    const float4* src = (const float4*)(in + w * DIM) + lane * 2;
    float4 v0 = src[0], v1 = src[1];
    float ss = v0.x*v0.x + v0.y*v0.y + v0.z*v0.z + v0.w*v0.w
             + v1.x*v1.x + v1.y*v1.y + v1.z*v1.z + v1.w*v1.w;
    #pragma unroll
    for (int o = 16; o; o >>= 1) ss += __shfl_xor_sync(0xFFFFFFFFu, ss, o);
    const float sc = 1.0f / fmaxf(sqrtf(ss), 1e-8f);
    __half2 hp[4];
    hp[0] = __floats2half2_rn(v0.x*sc, v0.y*sc);
    hp[1] = __floats2half2_rn(v0.z*sc, v0.w*sc);
    hp[2] = __floats2half2_rn(v1.x*sc, v1.y*sc);
    hp[3] = __floats2half2_rn(v1.z*sc, v1.w*sc);
    __half* dst = which ? g_Yhi : g_Xhi;
    *(uint4*)(dst + w * DIM + lane * 8) = *(uint4*)hp;
}

// ---------------- persistent HMMA GEMM + running-min -----------------------
__global__ void __launch_bounds__(256, 1) gemm_min_kernel() {
    extern __shared__ char smem[];
    const uint32_t sb = smem_u32(smem);
    const int tid = threadIdx.x, lane = tid & 31, wid = tid >> 5;
    const int warp_m = wid & 1;       // 2 warps in M (64 each)
    const int warp_n = wid >> 1;      // 4 warps in N (32 each)
    const float INF = __int_as_float(0x7f800000);

    const int bid = blockIdx.x;
    const int u0 = (bid * UNITS) / GRID, u1 = ((bid + 1) * UNITS) / GRID;
    const int c0 = u0 * 4, c1 = u1 * 4;
    int cur_nt = u0 >> 6;

    const uint64_t xh = gmem_u64(g_Xhi), yh = gmem_u64(g_Yhi);

    auto load_A = [&](int nt) {
        int nBase = nt * 128;
        #pragma unroll 4
        for (int i = 0; i < 16; i++) {
            int idx = tid + 256 * i;
            int kc = idx >> 10, rem = idx & 1023;
            int row = rem >> 3, seg = rem & 7;
            uint64_t src = xh + 2ull * ((uint64_t)(nBase + row) * DIM + kc * 64 + seg * 8);
            uint32_t dst = sb + SM_A + kc * 16384 + SWZ128(row * 128 + seg * 16);
            CPASYNC16(dst, src);
        }
        CP_COMMIT(); CP_WAIT(0);
        __syncthreads();
    };

    auto issue_chunk = [&](int ci) {
        int s = ci % NSTAGE, mt = (ci >> 2) & 63, kc = ci & 3;
        int mBase = mt * 128;
        #pragma unroll
        for (int i = 0; i < 4; i++) {
            int idx = tid + 256 * i;
            int row = idx >> 3, seg = idx & 7;
            uint64_t src = yh + 2ull * ((uint64_t)(mBase + row) * DIM + kc * 64 + seg * 8);
            uint32_t dst = sb + SM_B + s * 16384 + SWZ128(row * 128 + seg * 16);
            CPASYNC16(dst, src);
        }
    };

    // ---- per-thread ldmatrix address components ----
    const uint32_t xor7 = (lane & 7) << 4;
    const int aq = lane >> 3;
    const uint32_t a_k16 = (aq >> 1) << 4;
    const uint32_t b_k16 = ((lane >> 3) & 1) << 4;
    uint32_t rowA[4], rowB[2];
    #pragma unroll
    for (int mt = 0; mt < 4; mt++)
        rowA[mt] = (uint32_t)(warp_m * 64 + mt * 16 + ((aq & 1) << 3) + (lane & 7)) * 128;
    #pragma unroll
    for (int g = 0; g < 2; g++)
        rowB[g] = (uint32_t)(warp_n * 32 + g * 16 + (((lane >> 4) & 1) << 3) + (lane & 7)) * 128;

    float acc[4][4][4];
    #pragma unroll
    for (int mt = 0; mt < 4; mt++)
        #pragma unroll
        for (int nt = 0; nt < 4; nt++)
            #pragma unroll
            for (int e = 0; e < 4; e++) acc[mt][nt][e] = 0.0f;
    float rowmin[8], rowcex[8];
    #pragma unroll
    for (int i = 0; i < 8; i++) { rowmin[i] = INF; rowcex[i] = INF; }

    auto flush = [&](int nt) {
        __syncthreads();
        float* redM = (float*)smem;             // reuse A region: [128][16] x2
        float* redC = redM + 128 * 16;
        const int slot = warp_n * 4 + (lane & 3);
        #pragma unroll
        for (int i = 0; i < 8; i++) {
            int nl = warp_m * 64 + (i >> 1) * 16 + (i & 1) * 8 + (lane >> 2);
            redM[nl * 16 + slot] = rowmin[i];
            redC[nl * 16 + slot] = rowcex[i];
            rowmin[i] = INF; rowcex[i] = INF;
        }
        __syncthreads();
        if (tid < 128) {
            float m = INF, c = INF;
            #pragma unroll
            for (int k = 0; k < 16; k++) {
                m = fminf(m, redM[tid * 16 + k]);
                c = fminf(c, redC[tid * 16 + k]);
            }
            if (m < INF) atomicMinF(&g_minM[nt * 128 + tid], m);
            if (c < INF) atomicMinF(&g_cex [nt * 128 + tid], c);
        }
        __syncthreads();
    };

    load_A(cur_nt);
    #pragma unroll
    for (int j = 0; j < 4; j++) { issue_chunk(c0 + j); CP_COMMIT(); }

    #pragma unroll 1
    for (int ci = c0; ci < c1; ci++) {
        if ((ci & 3) == 0) {
            int nt = ci >> 8;                    // (ci/4)/64
            if (nt != cur_nt) {
                flush(cur_nt);
                CP_WAIT(0); __syncthreads();
                load_A(nt);
                cur_nt = nt;
            }
        }
        CP_WAIT(3);
        __syncthreads();
        if (ci + 4 < c1) issue_chunk(ci + 4);
        CP_COMMIT();

        const int s = ci % NSTAGE, kc = ci & 3;
        const uint32_t aHi = sb + SM_A + kc * 16384;
        const uint32_t bHi = sb + SM_B + s * 16384;

        #pragma unroll
        for (int ks = 0; ks < 4; ks++) {
            const uint32_t kbA = ((uint32_t)(ks * 32) + a_k16) ^ xor7;
            const uint32_t kbB = ((uint32_t)(ks * 32) + b_k16) ^ xor7;
            uint32_t Ah[4][4], Bh[4][2];
            #pragma unroll
            for (int g = 0; g < 2; g++) {
                uint32_t r[4];
                ldsm_x4(r, bHi + rowB[g] + kbB);
                Bh[2*g][0] = r[0]; Bh[2*g][1] = r[1]; Bh[2*g+1][0] = r[2]; Bh[2*g+1][1] = r[3];
            }
            #pragma unroll
            for (int mt = 0; mt < 4; mt++)
                ldsm_x4(Ah[mt], aHi + rowA[mt] + kbA);
            #pragma unroll
            for (int mt = 0; mt < 4; mt++)
                #pragma unroll
                for (int nt = 0; nt < 4; nt++)
                    mma16816(acc[mt][nt], Ah[mt], Bh[nt]);
        }

        if ((ci & 3) == 3) {   // m-tile complete: fold into running row-mins
            #pragma unroll
            for (int mt = 0; mt < 4; mt++)
                #pragma unroll
                for (int nt = 0; nt < 4; nt++)
                    #pragma unroll
                    for (int e = 0; e < 4; e++) {
                        float M = acc[mt][nt][e];
                        acc[mt][nt][e] = 0.0f;
                        int ri = mt * 2 + (e >> 1);
                        if (M > 0.5f) {      // cold exact path (monotonicity edge)
                            float z = (M - 1.0f) * INVS;
                            float lp = fmaf(-0.5f * z, z, LOGC);
                            rowcex[ri] = fminf(rowcex[ri], -expf(lp) * lp);
                        } else {
                            rowmin[ri] = fminf(rowmin[ri], M);
                        }
                    }
        }
    }
    flush(cur_nt);
}

// ---------------- final combine -------------------------------------------
__global__ void __launch_bounds__(256) combine_kernel(float* __restrict__ out) {
    int n = blockIdx.x * 256 + threadIdx.x;
    float m  = g_minM[n];
    float ce = g_cex[n];
    float C = __int_as_float(0x7f800000);
    if (m < 2.0f) {
        float z = (m - 1.0f) * INVS;
        float lp = fmaf(-0.5f * z, z, LOGC);
        C = -expf(lp) * lp;
    }
    out[n] = fminf(C, ce);
}

// ---------------------------------------------------------------------------
extern "C" void kernel_launch(void* const* d_in, const int* in_sizes, int n_in,
                              void* d_out, int out_size) {
    const float* Ex = (const float*)d_in[0];
    const float* Ey = (const float*)d_in[1];
    float* out = (float*)d_out;

    init_kernel<<<NROWS / 256, 256>>>();
    norm_kernel<<<NROWS / 8, 256>>>(Ex, 0);
    norm_kernel<<<NROWS / 8, 256>>>(Ey, 1);

    cudaFuncSetAttribute(gemm_min_kernel,
                         cudaFuncAttributeMaxDynamicSharedMemorySize, SMEM_TOTAL);
    gemm_min_kernel<<<GRID, 256, SMEM_TOTAL>>>();

    combine_kernel<<<NROWS / 256, 256>>>(out);
}